// round 1
// baseline (speedup 1.0000x reference)
#include <cuda_runtime.h>
#include <cuda_bf16.h>
#include <cstdint>

#define BATCH 2048
#define EMBED 2048
#define NCLS  50257
#define EPS   0.1f

#define BM 128
#define BN 128
#define BK 32
#define KS 40               // smem row stride in bf16 elems (BK + 8 pad -> 80B, coprime w/ 128B phases)
#define NKT (EMBED / BK)    // 64
#define NCH ((NCLS + BN - 1) / BN)   // 393

// ---------------- device scratch (no runtime allocation allowed) ----------------
__device__ __nv_bfloat16 g_Wbf[(size_t)NCLS * EMBED];   // ~206 MB
__device__ __nv_bfloat16 g_Ebf[(size_t)BATCH * EMBED];  // 8 MB
__device__ float g_sumexp[(size_t)NCH * BATCH];
__device__ float g_sumlog[(size_t)NCH * BATCH];
__device__ float g_labellogit[BATCH];
__device__ float g_part[8];

// ---------------- fp32 -> bf16 conversion ----------------
__global__ void cvt_W(const float4* __restrict__ src) {
    size_t i = (size_t)blockIdx.x * blockDim.x + threadIdx.x;
    size_t n4 = (size_t)NCLS * EMBED / 4;
    if (i < n4) {
        float4 v = src[i];
        __nv_bfloat162* dst = reinterpret_cast<__nv_bfloat162*>(g_Wbf);
        dst[2 * i]     = __float22bfloat162_rn(make_float2(v.x, v.y));
        dst[2 * i + 1] = __float22bfloat162_rn(make_float2(v.z, v.w));
    }
}

__global__ void cvt_E(const float4* __restrict__ src) {
    size_t i = (size_t)blockIdx.x * blockDim.x + threadIdx.x;
    size_t n4 = (size_t)BATCH * EMBED / 4;
    if (i < n4) {
        float4 v = src[i];
        __nv_bfloat162* dst = reinterpret_cast<__nv_bfloat162*>(g_Ebf);
        dst[2 * i]     = __float22bfloat162_rn(make_float2(v.x, v.y));
        dst[2 * i + 1] = __float22bfloat162_rn(make_float2(v.z, v.w));
    }
}

// ---------------- PTX helpers ----------------
__device__ __forceinline__ void ldsm4(uint32_t* r, uint32_t addr) {
    asm volatile("ldmatrix.sync.aligned.m8n8.x4.shared.b16 {%0,%1,%2,%3}, [%4];\n"
                 : "=r"(r[0]), "=r"(r[1]), "=r"(r[2]), "=r"(r[3]) : "r"(addr));
}

__device__ __forceinline__ void mma16816(float* c, const uint32_t* a, uint32_t b0, uint32_t b1) {
    asm volatile("mma.sync.aligned.m16n8k16.row.col.f32.bf16.bf16.f32 "
                 "{%0,%1,%2,%3},{%4,%5,%6,%7},{%8,%9},{%0,%1,%2,%3};\n"
                 : "+f"(c[0]), "+f"(c[1]), "+f"(c[2]), "+f"(c[3])
                 : "r"(a[0]), "r"(a[1]), "r"(a[2]), "r"(a[3]), "r"(b0), "r"(b1));
}

__device__ __forceinline__ void cp16(uint32_t dst, const void* src) {
    asm volatile("cp.async.cg.shared.global [%0], [%1], 16;\n" :: "r"(dst), "l"(src) : "memory");
}
__device__ __forceinline__ void cp16z(uint32_t dst, const void* src, int srcBytes) {
    asm volatile("cp.async.cg.shared.global [%0], [%1], 16, %2;\n"
                 :: "r"(dst), "l"(src), "r"(srcBytes) : "memory");
}

// ---------------- fused GEMM + partial CE reductions ----------------
__global__ __launch_bounds__(256, 2)
void gemm_ce_kernel(const int* __restrict__ labels) {
    __shared__ __nv_bfloat16 Asm[2][BM * KS];
    __shared__ __nv_bfloat16 Bsm[2][BN * KS];
    __shared__ float redSE[2][BM];
    __shared__ float redSL[2][BM];

    const int tid = threadIdx.x;
    const int chunk = blockIdx.x;            // class chunk
    const int rowBase = blockIdx.y * BM;     // batch rows
    const int cBase = chunk * BN;
    const int wid = tid >> 5, lane = tid & 31;
    const int warpM = wid & 3, warpN = wid >> 2;   // 4 x 2 warps -> 32x64 per warp

    const uint32_t aBase = (uint32_t)__cvta_generic_to_shared(Asm);
    const uint32_t bBase = (uint32_t)__cvta_generic_to_shared(Bsm);
    const int STAGE_BYTES = BM * KS * 2;     // 10240

    // per-thread load assignments: 512 16B chunks per tile, 2 per thread
    const int r0i = (tid + 0)   >> 2, c0i = (tid + 0)   & 3;
    const int r1i = (tid + 256) >> 2, c1i = (tid + 256) & 3;

    auto loadA = [&](int s, int kt) {
        const __nv_bfloat16* gA = g_Ebf + (size_t)rowBase * EMBED + kt * BK;
        cp16(aBase + s * STAGE_BYTES + r0i * 80 + c0i * 16, gA + (size_t)r0i * EMBED + c0i * 8);
        cp16(aBase + s * STAGE_BYTES + r1i * 80 + c1i * 16, gA + (size_t)r1i * EMBED + c1i * 8);
    };
    auto loadB = [&](int s, int kt) {
        {
            int crow = cBase + r0i;
            int p = (crow < NCLS) ? 16 : 0;
            int cc = crow < NCLS ? crow : (NCLS - 1);
            cp16z(bBase + s * STAGE_BYTES + r0i * 80 + c0i * 16,
                  g_Wbf + (size_t)cc * EMBED + kt * BK + c0i * 8, p);
        }
        {
            int crow = cBase + r1i;
            int p = (crow < NCLS) ? 16 : 0;
            int cc = crow < NCLS ? crow : (NCLS - 1);
            cp16z(bBase + s * STAGE_BYTES + r1i * 80 + c1i * 16,
                  g_Wbf + (size_t)cc * EMBED + kt * BK + c1i * 8, p);
        }
    };

    float acc[2][8][4];
    #pragma unroll
    for (int mt = 0; mt < 2; mt++)
        #pragma unroll
        for (int nt = 0; nt < 8; nt++)
            #pragma unroll
            for (int v = 0; v < 4; v++) acc[mt][nt][v] = 0.f;

    loadA(0, 0); loadB(0, 0);
    asm volatile("cp.async.commit_group;\n" ::: "memory");

    #pragma unroll 1
    for (int kt = 0; kt < NKT; kt++) {
        if (kt + 1 < NKT) {
            int s = (kt + 1) & 1;
            loadA(s, kt + 1); loadB(s, kt + 1);
            asm volatile("cp.async.commit_group;\n" ::: "memory");
            asm volatile("cp.async.wait_group 1;\n" ::: "memory");
        } else {
            asm volatile("cp.async.wait_group 0;\n" ::: "memory");
        }
        __syncthreads();

        const int s = kt & 1;
        const uint32_t aS = aBase + s * STAGE_BYTES;
        const uint32_t bS = bBase + s * STAGE_BYTES;

        #pragma unroll
        for (int kk = 0; kk < 2; kk++) {
            uint32_t afr[2][4];
            #pragma unroll
            for (int mt = 0; mt < 2; mt++) {
                int row = warpM * 32 + mt * 16 + (lane & 15);
                ldsm4(afr[mt], aS + row * 80 + (kk * 2 + (lane >> 4)) * 16);
            }
            uint32_t bfr[4][4];
            #pragma unroll
            for (int ng = 0; ng < 4; ng++) {
                int nrow = warpN * 64 + ng * 16 + ((lane >> 4) << 3) + (lane & 7);
                ldsm4(bfr[ng], bS + nrow * 80 + (kk * 2 + ((lane >> 3) & 1)) * 16);
            }
            #pragma unroll
            for (int mt = 0; mt < 2; mt++)
                #pragma unroll
                for (int ng = 0; ng < 4; ng++) {
                    mma16816(acc[mt][ng * 2 + 0], afr[mt], bfr[ng][0], bfr[ng][1]);
                    mma16816(acc[mt][ng * 2 + 1], afr[mt], bfr[ng][2], bfr[ng][3]);
                }
        }
        __syncthreads();
    }

    // ---------------- fused epilogue: per-(row, chunk) partials ----------------
    const int colBase = cBase + warpN * 64;
    #pragma unroll
    for (int mt = 0; mt < 2; mt++) {
        int rLoc0 = warpM * 32 + mt * 16 + (lane >> 2);
        int rLoc1 = rLoc0 + 8;
        int gr0 = rowBase + rLoc0, gr1 = rowBase + rLoc1;
        int lbl0 = labels[gr0], lbl1 = labels[gr1];
        float se0 = 0.f, sl0 = 0.f, se1 = 0.f, sl1 = 0.f;
        #pragma unroll
        for (int nt = 0; nt < 8; nt++) {
            int c0 = colBase + nt * 8 + ((lane & 3) << 1);
            int c1 = c0 + 1;
            float v00 = acc[mt][nt][0], v01 = acc[mt][nt][1];
            float v10 = acc[mt][nt][2], v11 = acc[mt][nt][3];
            if (c0 < NCLS) {
                se0 += __expf(v00); sl0 += v00;
                se1 += __expf(v10); sl1 += v10;
                if (c0 == lbl0) g_labellogit[gr0] = v00;
                if (c0 == lbl1) g_labellogit[gr1] = v10;
            }
            if (c1 < NCLS) {
                se0 += __expf(v01); sl0 += v01;
                se1 += __expf(v11); sl1 += v11;
                if (c1 == lbl0) g_labellogit[gr0] = v01;
                if (c1 == lbl1) g_labellogit[gr1] = v11;
            }
        }
        #pragma unroll
        for (int m = 1; m < 4; m <<= 1) {
            se0 += __shfl_xor_sync(0xffffffffu, se0, m);
            sl0 += __shfl_xor_sync(0xffffffffu, sl0, m);
            se1 += __shfl_xor_sync(0xffffffffu, se1, m);
            sl1 += __shfl_xor_sync(0xffffffffu, sl1, m);
        }
        if ((lane & 3) == 0) {
            redSE[warpN][rLoc0] = se0; redSL[warpN][rLoc0] = sl0;
            redSE[warpN][rLoc1] = se1; redSL[warpN][rLoc1] = sl1;
        }
    }
    __syncthreads();
    if (tid < BM) {
        float se = redSE[0][tid] + redSE[1][tid];
        float sl = redSL[0][tid] + redSL[1][tid];
        g_sumexp[(size_t)chunk * BATCH + rowBase + tid] = se;
        g_sumlog[(size_t)chunk * BATCH + rowBase + tid] = sl;
    }
}

// ---------------- final reductions ----------------
__global__ void row_reduce_kernel() {
    int row = blockIdx.x * 256 + threadIdx.x;
    float S = 0.f, L = 0.f;
    for (int j = 0; j < NCH; j++) {
        S += g_sumexp[(size_t)j * BATCH + row];
        L += g_sumlog[(size_t)j * BATCH + row];
    }
    // per-sample = lse - (1-eps)*logit_y - eps*(sum logits)/C
    float per = logf(S) - (1.0f - EPS) * g_labellogit[row] - EPS * (L * (1.0f / (float)NCLS));
    __shared__ float sm[256];
    sm[threadIdx.x] = per;
    __syncthreads();
    for (int s = 128; s > 0; s >>= 1) {
        if (threadIdx.x < s) sm[threadIdx.x] += sm[threadIdx.x + s];
        __syncthreads();
    }
    if (threadIdx.x == 0) g_part[blockIdx.x] = sm[0];
}

__global__ void final_kernel(float* __restrict__ out) {
    if (threadIdx.x == 0) {
        float s = 0.f;
        for (int i = 0; i < 8; i++) s += g_part[i];
        out[0] = s * (1.0f / (float)BATCH);
    }
}

// ---------------- entry ----------------
extern "C" void kernel_launch(void* const* d_in, const int* in_sizes, int n_in,
                              void* d_out, int out_size) {
    const float* E = (const float*)d_in[0];
    const int* labels = (const int*)d_in[1];
    const float* W = (const float*)d_in[2];
    float* out = (float*)d_out;

    size_t nW4 = (size_t)NCLS * EMBED / 4;
    size_t nE4 = (size_t)BATCH * EMBED / 4;
    cvt_W<<<(unsigned)((nW4 + 255) / 256), 256>>>((const float4*)W);
    cvt_E<<<(unsigned)((nE4 + 255) / 256), 256>>>((const float4*)E);

    dim3 grid(NCH, BATCH / BM);   // 393 x 16
    gemm_ce_kernel<<<grid, 256>>>(labels);

    row_reduce_kernel<<<BATCH / 256, 256>>>();
    final_kernel<<<1, 32>>>(out);
}

// round 7
// speedup vs baseline: 1.3506x; 1.3506x over previous
#include <cuda_runtime.h>
#include <cuda_bf16.h>
#include <cstdint>

#define BATCH 2048
#define EMBED 2048
#define NCLS  50257
#define EPS   0.1f

#define BM 128
#define BN 128
#define BK 64                      // 64 bf16 = 128B row (one swizzle phase)
#define NKT (EMBED / BK)           // 32
#define NCH ((NCLS + BN - 1) / BN) // 393
#define NSTAGE 3
#define A_BYTES (BM * BK * 2)      // 16384
#define B_BYTES (BN * BK * 2)      // 16384
#define STG_BYTES (A_BYTES + B_BYTES)           // 32768
#define SMEM_TOTAL (NSTAGE * STG_BYTES)         // 98304
#define NRED 16

// ---------------- device scratch ----------------
__device__ __nv_bfloat16 g_Wbf[(size_t)NCLS * EMBED];
__device__ __nv_bfloat16 g_Ebf[(size_t)BATCH * EMBED];
__device__ float g_sumexp[(size_t)NCH * BATCH];
__device__ float g_sumlog[(size_t)NCH * BATCH];
__device__ float g_SE2[(size_t)NRED * BATCH];
__device__ float g_SL2[(size_t)NRED * BATCH];
__device__ float g_labellogit[BATCH];
__device__ float g_part[8];

// ---------------- fp32 -> bf16 ----------------
__global__ void cvt_W(const float4* __restrict__ src) {
    size_t i = (size_t)blockIdx.x * blockDim.x + threadIdx.x;
    size_t n4 = (size_t)NCLS * EMBED / 4;
    if (i < n4) {
        float4 v = src[i];
        __nv_bfloat162* dst = reinterpret_cast<__nv_bfloat162*>(g_Wbf);
        dst[2 * i]     = __float22bfloat162_rn(make_float2(v.x, v.y));
        dst[2 * i + 1] = __float22bfloat162_rn(make_float2(v.z, v.w));
    }
}
__global__ void cvt_E(const float4* __restrict__ src) {
    size_t i = (size_t)blockIdx.x * blockDim.x + threadIdx.x;
    size_t n4 = (size_t)BATCH * EMBED / 4;
    if (i < n4) {
        float4 v = src[i];
        __nv_bfloat162* dst = reinterpret_cast<__nv_bfloat162*>(g_Ebf);
        dst[2 * i]     = __float22bfloat162_rn(make_float2(v.x, v.y));
        dst[2 * i + 1] = __float22bfloat162_rn(make_float2(v.z, v.w));
    }
}

// ---------------- PTX helpers ----------------
__device__ __forceinline__ void ldsm4(uint32_t* r, uint32_t addr) {
    asm volatile("ldmatrix.sync.aligned.m8n8.x4.shared.b16 {%0,%1,%2,%3}, [%4];\n"
                 : "=r"(r[0]), "=r"(r[1]), "=r"(r[2]), "=r"(r[3]) : "r"(addr));
}
__device__ __forceinline__ void mma16816(float* c, const uint32_t* a, uint32_t b0, uint32_t b1) {
    asm volatile("mma.sync.aligned.m16n8k16.row.col.f32.bf16.bf16.f32 "
                 "{%0,%1,%2,%3},{%4,%5,%6,%7},{%8,%9},{%0,%1,%2,%3};\n"
                 : "+f"(c[0]), "+f"(c[1]), "+f"(c[2]), "+f"(c[3])
                 : "r"(a[0]), "r"(a[1]), "r"(a[2]), "r"(a[3]), "r"(b0), "r"(b1));
}
__device__ __forceinline__ void cp16(uint32_t dst, const void* src) {
    asm volatile("cp.async.cg.shared.global [%0], [%1], 16;\n" :: "r"(dst), "l"(src) : "memory");
}
__device__ __forceinline__ void cp16z(uint32_t dst, const void* src, int srcBytes) {
    asm volatile("cp.async.cg.shared.global [%0], [%1], 16, %2;\n"
                 :: "r"(dst), "l"(src), "r"(srcBytes) : "memory");
}

// ---------------- fused GEMM + partial CE ----------------
__global__ __launch_bounds__(256, 2)
void gemm_ce_kernel(const int* __restrict__ labels) {
    extern __shared__ __align__(1024) char dynsm[];
    __shared__ float redSE[2][BM];
    __shared__ float redSL[2][BM];

    const int tid = threadIdx.x;
    const int rowBase = blockIdx.x * BM;   // x = rowblock (fast) -> wave shares W chunk
    const int chunk = blockIdx.y;          // y = class chunk
    const int cBase = chunk * BN;
    const int wid = tid >> 5, lane = tid & 31;
    const int warpM = wid & 3, warpN = wid >> 2;   // 4 x 2 warps -> 32x64 each

    const uint32_t smb = (uint32_t)__cvta_generic_to_shared(dynsm);
    const __nv_bfloat16* gA = g_Ebf + (size_t)rowBase * EMBED;

    auto issueStage = [&](int kt) {
        const int s = kt % NSTAGE;
        const uint32_t stA = smb + s * STG_BYTES;
        const uint32_t stB = stA + A_BYTES;
        const int kOff = kt * BK;
        #pragma unroll
        for (int i = 0; i < 4; i++) {          // A: 1024 16B chunks / 256 thr
            int idx = tid + i * 256;
            int r = idx >> 3, c = idx & 7;
            cp16(stA + r * 128 + ((c ^ (r & 7)) << 4),
                 gA + (size_t)r * EMBED + kOff + c * 8);
        }
        #pragma unroll
        for (int i = 0; i < 4; i++) {          // B
            int idx = tid + i * 256;
            int r = idx >> 3, c = idx & 7;
            int crow = cBase + r;
            int p = (crow < NCLS) ? 16 : 0;
            int cc = (crow < NCLS) ? crow : (NCLS - 1);
            cp16z(stB + r * 128 + ((c ^ (r & 7)) << 4),
                  g_Wbf + (size_t)cc * EMBED + kOff + c * 8, p);
        }
        asm volatile("cp.async.commit_group;\n" ::: "memory");
    };

    float acc[2][8][4];
    #pragma unroll
    for (int mt = 0; mt < 2; mt++)
        #pragma unroll
        for (int nt = 0; nt < 8; nt++)
            #pragma unroll
            for (int v = 0; v < 4; v++) acc[mt][nt][v] = 0.f;

    issueStage(0);
    issueStage(1);

    #pragma unroll 1
    for (int kt = 0; kt < NKT; kt++) {
        if (kt < NKT - 2) asm volatile("cp.async.wait_group 1;\n" ::: "memory");
        else              asm volatile("cp.async.wait_group 0;\n" ::: "memory");
        __syncthreads();
        if (kt + 2 < NKT) issueStage(kt + 2);

        const int s = kt % NSTAGE;
        const uint32_t aS = smb + s * STG_BYTES;
        const uint32_t bS = aS + A_BYTES;

        #pragma unroll
        for (int kk = 0; kk < 4; kk++) {
            uint32_t afr[2][4];
            #pragma unroll
            for (int mt = 0; mt < 2; mt++) {
                int row = warpM * 32 + mt * 16 + (lane & 15);
                int kcol = kk * 2 + (lane >> 4);
                ldsm4(afr[mt], aS + row * 128 + ((kcol ^ (row & 7)) << 4));
            }
            uint32_t bfr[4][4];
            #pragma unroll
            for (int ng = 0; ng < 4; ng++) {
                int nrow = warpN * 64 + ng * 16 + ((lane >> 4) << 3) + (lane & 7);
                int kcol = kk * 2 + ((lane >> 3) & 1);
                ldsm4(bfr[ng], bS + nrow * 128 + ((kcol ^ (nrow & 7)) << 4));
            }
            #pragma unroll
            for (int mt = 0; mt < 2; mt++)
                #pragma unroll
                for (int ng = 0; ng < 4; ng++) {
                    mma16816(acc[mt][ng * 2 + 0], afr[mt], bfr[ng][0], bfr[ng][1]);
                    mma16816(acc[mt][ng * 2 + 1], afr[mt], bfr[ng][2], bfr[ng][3]);
                }
        }
    }
    __syncthreads();

    // ---------------- fused epilogue ----------------
    const int colBase = cBase + warpN * 64;
    #pragma unroll
    for (int mt = 0; mt < 2; mt++) {
        int rLoc0 = warpM * 32 + mt * 16 + (lane >> 2);
        int rLoc1 = rLoc0 + 8;
        int gr0 = rowBase + rLoc0, gr1 = rowBase + rLoc1;
        int lbl0 = labels[gr0], lbl1 = labels[gr1];
        float se0 = 0.f, sl0 = 0.f, se1 = 0.f, sl1 = 0.f;
        #pragma unroll
        for (int nt = 0; nt < 8; nt++) {
            int c0 = colBase + nt * 8 + ((lane & 3) << 1);
            int c1 = c0 + 1;
            float v00 = acc[mt][nt][0], v01 = acc[mt][nt][1];
            float v10 = acc[mt][nt][2], v11 = acc[mt][nt][3];
            if (c0 < NCLS) {
                se0 += __expf(v00); sl0 += v00;
                se1 += __expf(v10); sl1 += v10;
                if (c0 == lbl0) g_labellogit[gr0] = v00;
                if (c0 == lbl1) g_labellogit[gr1] = v10;
            }
            if (c1 < NCLS) {
                se0 += __expf(v01); sl0 += v01;
                se1 += __expf(v11); sl1 += v11;
                if (c1 == lbl0) g_labellogit[gr0] = v01;
                if (c1 == lbl1) g_labellogit[gr1] = v11;
            }
        }
        #pragma unroll
        for (int m = 1; m < 4; m <<= 1) {
            se0 += __shfl_xor_sync(0xffffffffu, se0, m);
            sl0 += __shfl_xor_sync(0xffffffffu, sl0, m);
            se1 += __shfl_xor_sync(0xffffffffu, se1, m);
            sl1 += __shfl_xor_sync(0xffffffffu, sl1, m);
        }
        if ((lane & 3) == 0) {
            redSE[warpN][rLoc0] = se0; redSL[warpN][rLoc0] = sl0;
            redSE[warpN][rLoc1] = se1; redSL[warpN][rLoc1] = sl1;
        }
    }
    __syncthreads();
    if (tid < BM) {
        float se = redSE[0][tid] + redSE[1][tid];
        float sl = redSL[0][tid] + redSL[1][tid];
        g_sumexp[(size_t)chunk * BATCH + rowBase + tid] = se;
        g_sumlog[(size_t)chunk * BATCH + rowBase + tid] = sl;
    }
}

// ---------------- reductions ----------------
__global__ void reduce1_kernel() {
    int row = blockIdx.x * 256 + threadIdx.x;
    int g = blockIdx.y;
    float S = 0.f, L = 0.f;
    for (int j = g; j < NCH; j += NRED) {
        S += g_sumexp[(size_t)j * BATCH + row];
        L += g_sumlog[(size_t)j * BATCH + row];
    }
    g_SE2[(size_t)g * BATCH + row] = S;
    g_SL2[(size_t)g * BATCH + row] = L;
}

__global__ void reduce2_kernel() {
    int row = blockIdx.x * 256 + threadIdx.x;
    float S = 0.f, L = 0.f;
    #pragma unroll
    for (int g = 0; g < NRED; g++) {
        S += g_SE2[(size_t)g * BATCH + row];
        L += g_SL2[(size_t)g * BATCH + row];
    }
    float per = logf(S) - (1.0f - EPS) * g_labellogit[row] - EPS * (L * (1.0f / (float)NCLS));
    __shared__ float sm[256];
    sm[threadIdx.x] = per;
    __syncthreads();
    for (int s = 128; s > 0; s >>= 1) {
        if (threadIdx.x < s) sm[threadIdx.x] += sm[threadIdx.x + s];
        __syncthreads();
    }
    if (threadIdx.x == 0) g_part[blockIdx.x] = sm[0];
}

__global__ void final_kernel(float* __restrict__ out) {
    if (threadIdx.x == 0) {
        float s = 0.f;
        for (int i = 0; i < 8; i++) s += g_part[i];
        out[0] = s * (1.0f / (float)BATCH);
    }
}

// ---------------- entry ----------------
extern "C" void kernel_launch(void* const* d_in, const int* in_sizes, int n_in,
                              void* d_out, int out_size) {
    const float* E = (const float*)d_in[0];
    const int* labels = (const int*)d_in[1];
    const float* W = (const float*)d_in[2];
    float* out = (float*)d_out;

    static int attr_set = 0;
    if (!attr_set) {
        cudaFuncSetAttribute(gemm_ce_kernel, cudaFuncAttributeMaxDynamicSharedMemorySize,
                             SMEM_TOTAL);
        attr_set = 1;
    }

    size_t nW4 = (size_t)NCLS * EMBED / 4;
    size_t nE4 = (size_t)BATCH * EMBED / 4;
    cvt_W<<<(unsigned)((nW4 + 255) / 256), 256>>>((const float4*)W);
    cvt_E<<<(unsigned)((nE4 + 255) / 256), 256>>>((const float4*)E);

    dim3 grid(BATCH / BM, NCH);   // 16 x 393 ; x fast -> wave shares W chunk via L2
    gemm_ce_kernel<<<grid, 256, SMEM_TOTAL>>>(labels);

    dim3 rg(BATCH / 256, NRED);
    reduce1_kernel<<<rg, 256>>>();
    reduce2_kernel<<<BATCH / 256, 256>>>();
    final_kernel<<<1, 32>>>(out);
}